// round 3
// baseline (speedup 1.0000x reference)
#include <cuda_runtime.h>
#include <cuda_bf16.h>

// SiLU y = x*sigmoid(x), streaming fp32. R3: 8x float4 per thread,
// all loads front-batched (MLP_p1=8), streaming cache hints.

__device__ __forceinline__ float silu1(float x) {
    return x * (1.0f / (1.0f + __expf(-x)));
}

__device__ __forceinline__ float4 silu4(float4 v) {
    float4 r;
    r.x = silu1(v.x);
    r.y = silu1(v.y);
    r.z = silu1(v.z);
    r.w = silu1(v.w);
    return r;
}

#define VPT 8  // float4s per thread

__global__ void __launch_bounds__(256)
silu_kernel_v4x8(const float4* __restrict__ in,
                 float4* __restrict__ out,
                 int n4) {
    int base = blockIdx.x * (blockDim.x * VPT) + threadIdx.x;

    if (base + (VPT - 1) * blockDim.x < n4) {
        float4 v[VPT];
        #pragma unroll
        for (int k = 0; k < VPT; k++)
            v[k] = __ldcs(&in[base + k * blockDim.x]);
        #pragma unroll
        for (int k = 0; k < VPT; k++)
            __stcs(&out[base + k * blockDim.x], silu4(v[k]));
    } else {
        #pragma unroll
        for (int k = 0; k < VPT; k++) {
            int i = base + k * blockDim.x;
            if (i < n4) __stcs(&out[i], silu4(__ldcs(&in[i])));
        }
    }
}

__global__ void silu_kernel_tail(const float* __restrict__ in,
                                 float* __restrict__ out,
                                 int start, int n) {
    int i = start + blockIdx.x * blockDim.x + threadIdx.x;
    if (i < n) out[i] = silu1(in[i]);
}

extern "C" void kernel_launch(void* const* d_in, const int* in_sizes, int n_in,
                              void* d_out, int out_size) {
    const float* x = (const float*)d_in[0];
    float* y = (float*)d_out;
    int n = in_sizes[0];

    int n4 = n / 4;
    if (n4 > 0) {
        int threads = 256;
        int per_block = threads * VPT;
        int blocks = (n4 + per_block - 1) / per_block;
        silu_kernel_v4x8<<<blocks, threads>>>((const float4*)x, (float4*)y, n4);
    }
    int rem = n - n4 * 4;
    if (rem > 0) {
        silu_kernel_tail<<<1, 256>>>(x, y, n4 * 4, n);
    }
}